// round 12
// baseline (speedup 1.0000x reference)
#include <cuda_runtime.h>
#include <cuda_fp16.h>
#include <stdint.h>

#define B_SZ     4096
#define D0       1024
#define D1       8192
#define D2       8192
#define D3       10240
#define NNEUR    (D1 + D2 + D3)     // 26624
#define KCLS     10
#define GRP      (D3 / KCLS)        // 1024
#define TAU      30.0f
#define ROWS     4
#define NTHREADS 1024
#define NWARP    (NTHREADS / 32)    // 32
#define CELLS    256                // 16 a-bank-pairs x 16 b-bank-pairs
#define CHUNK    1024
#define CAP      (CHUNK / CELLS)    // 4
#define NCHUNK   (NNEUR / CHUNK)    // 26
#define SCNSTR   40                 // 32 warps + pad

// -------- staging (original order) --------
__device__ uint32_t s_idx[NNEUR];
__device__ uint32_t s_c01[NNEUR];
__device__ uint32_t s_c23[NNEUR];
// -------- inverse perms (orig -> dealt pos, layer-local) --------
__device__ uint16_t d_inv1[D1];
__device__ uint16_t d_inv2[D2];
// -------- final metadata (dealt positions) --------
__device__ uint32_t g_idx[NNEUR];              // ia | (ib<<16), position-space
__device__ uint2    g_coef[NNEUR];             // {half2(c0,c1), half2(c2,c3)}

__constant__ float OPC[16][4] = {
    {0.f, 0.f, 0.f, 0.f}, {0.f, 0.f, 0.f, 1.f}, {0.f, 1.f, 0.f, -1.f}, {0.f, 1.f, 0.f, 0.f},
    {0.f, 0.f, 1.f, -1.f}, {0.f, 0.f, 1.f, 0.f}, {0.f, 1.f, 1.f, -2.f}, {0.f, 1.f, 1.f, -1.f},
    {1.f, -1.f, -1.f, 1.f}, {1.f, -1.f, -1.f, 2.f}, {1.f, 0.f, -1.f, 0.f}, {1.f, 0.f, -1.f, 1.f},
    {1.f, -1.f, 0.f, 0.f}, {1.f, -1.f, 0.f, 1.f}, {1.f, 0.f, 0.f, -1.f}, {1.f, 0.f, 0.f, 0.f}};

__global__ void precompute_kernel(
    const float* __restrict__ w1, const float* __restrict__ w2, const float* __restrict__ w3,
    const int* __restrict__ ia1, const int* __restrict__ ib1,
    const int* __restrict__ ia2, const int* __restrict__ ib2,
    const int* __restrict__ ia3, const int* __restrict__ ib3)
{
    int j = blockIdx.x * blockDim.x + threadIdx.x;
    if (j >= NNEUR) return;
    const float* w; int ia, ib;
    if (j < D1)            { w = w1 + (size_t)j * 16;               ia = ia1[j];            ib = ib1[j]; }
    else if (j < D1 + D2)  { int k = j - D1;      w = w2 + (size_t)k * 16; ia = ia2[k]; ib = ib2[k]; }
    else                   { int k = j - D1 - D2; w = w3 + (size_t)k * 16; ia = ia3[k]; ib = ib3[k]; }

    float v[16]; float m = -3.4e38f;
#pragma unroll
    for (int i = 0; i < 16; i++) { v[i] = w[i]; m = fmaxf(m, v[i]); }
    float s = 0.f;
#pragma unroll
    for (int i = 0; i < 16; i++) { v[i] = expf(v[i] - m); s += v[i]; }
    float inv = 1.f / s;
    float c0 = 0.f, c1 = 0.f, c2 = 0.f, c3 = 0.f;
#pragma unroll
    for (int i = 0; i < 16; i++) {
        float p = v[i] * inv;
        c0 = fmaf(p, OPC[i][0], c0);
        c1 = fmaf(p, OPC[i][1], c1);
        c2 = fmaf(p, OPC[i][2], c2);
        c3 = fmaf(p, OPC[i][3], c3);
    }
    s_idx[j] = (uint32_t)ia | ((uint32_t)ib << 16);
    __half2 h01 = __floats2half2_rn(c0, c1);
    __half2 h23 = __floats2half2_rn(c2, c3);
    s_c01[j] = *reinterpret_cast<uint32_t*>(&h01);
    s_c23[j] = *reinterpret_cast<uint32_t*>(&h23);
}

// ---- parallel bank-deal builder: 26 fully independent CTAs ------------------
// Cells are classified from RAW indices for all layers. This is exact for
// layer 1 (x is unpermuted) and approximate for layers 2/3 — valid because the
// deal formula p = (((s-t)&15) + 16m)*16 + t preserves p = a&15 (mod 16) for
// every unspilled neuron, so inv[a]&15 == a&15 for ~81% of sources. Cell
// classification affects only deal QUALITY; the permutation itself is exact.
// g_idx gets the raw packed indices here; a remap pass fixes layers 2/3.
__global__ void __launch_bounds__(1024, 1)
build_deal_kernel()
{
    __shared__ uint16_t off[CELLS * SCNSTR];
    __shared__ uint16_t chbase[CELLS * 4];
    __shared__ uint16_t csize[CELLS], exoff[CELLS], ufoff[CELLS];
    __shared__ uint16_t ufp[CHUNK];
    __shared__ int wte[8], wtu[8];

    const int tid  = threadIdx.x;
    const int lane = tid & 31;
    const int w    = tid >> 5;
    const uint32_t ltm = (1u << lane) - 1u;

    const int chunk = blockIdx.x;
    const int layer = (chunk < 8) ? 0 : ((chunk < 16) ? 1 : 2);
    const int layerBase = (layer == 0) ? 0 : ((layer == 1) ? D1 : (D1 + D2));
    const int baseL = (chunk - ((layer == 0) ? 0 : ((layer == 1) ? 8 : 16))) * CHUNK;
    const int gj = layerBase + baseL + tid;

    for (int i = tid; i < CELLS * SCNSTR / 2; i += 1024)
        reinterpret_cast<uint32_t*>(off)[i] = 0;
    __syncthreads();

    uint32_t pk  = s_idx[gj];
    uint32_t c01 = s_c01[gj];
    uint32_t c23 = s_c23[gj];

    int cell = (int)((pk & 15u) * 16u + ((pk >> 16) & 15u));
    uint32_t mask = __match_any_sync(0xffffffffu, cell);
    int lr = __popc(mask & ltm);
    if ((mask & ltm) == 0)
        off[cell * SCNSTR + w] = (uint16_t)__popc(mask);
    __syncthreads();

    {   // phase 1: per-(cell, 8-warp chunk) exclusive scan
        int c  = tid >> 2;
        int ch = tid & 3;
        int bo = c * SCNSTR + ch * 8;
        uint16_t run = 0;
#pragma unroll
        for (int i = 0; i < 8; i++) {
            uint16_t t = off[bo + i];
            off[bo + i] = run;
            run = (uint16_t)(run + t);
        }
        chbase[c * 4 + ch] = run;
    }
    __syncthreads();

    if (tid < CELLS) {   // phase 2: per-cell combine
        int c = tid; uint16_t bb = 0;
#pragma unroll
        for (int ch = 0; ch < 4; ch++) {
            uint16_t t = chbase[c * 4 + ch];
            chbase[c * 4 + ch] = bb;
            bb = (uint16_t)(bb + t);
        }
        csize[c] = bb;
        exoff[c] = (bb > CAP) ? (uint16_t)(bb - CAP) : 0;
        ufoff[c] = (bb < CAP) ? (uint16_t)(CAP - bb) : 0;
    }
    __syncthreads();

    {   // inclusive scans over 256 cells via warp shuffles
        int e = 0, u = 0;
        if (tid < CELLS) {
            e = exoff[tid]; u = ufoff[tid];
#pragma unroll
            for (int o = 1; o < 32; o <<= 1) {
                int pe = __shfl_up_sync(0xffffffffu, e, o);
                int pu = __shfl_up_sync(0xffffffffu, u, o);
                if (lane >= o) { e += pe; u += pu; }
            }
            if (lane == 31) { wte[w] = e; wtu[w] = u; }
        }
        __syncthreads();
        if (tid == 0) {
            int be = 0, bu = 0;
#pragma unroll
            for (int i = 0; i < 8; i++) {
                int te = wte[i], tu = wtu[i];
                wte[i] = be; wtu[i] = bu;
                be += te; bu += tu;
            }
        }
        __syncthreads();
        if (tid < CELLS) {
            exoff[tid] = (uint16_t)(e + wte[w]);
            ufoff[tid] = (uint16_t)(u + wtu[w]);
        }
    }
    __syncthreads();

    if (tid < CELLS) {   // emit unfilled dealt positions, grouped by cell
        int c = tid, t = c >> 4, s = c & 15;
        int sz  = csize[c];
        int ufc = (sz < CAP) ? CAP - sz : 0;
        int ub  = ufoff[c] - ufc;
        for (int m = sz; m < CAP; m++)
            ufp[ub + (m - sz)] = (uint16_t)((((s - t) & 15) + 16 * m) * 16 + t);
    }
    __syncthreads();

    {   // assign position + metadata write (raw indices; remap pass follows)
        int grank = off[cell * SCNSTR + w] + chbase[cell * 4 + (w >> 3)] + lr;
        int t = cell >> 4, s = cell & 15;
        int p;
        if (grank < CAP) {
            p = (((s - t) & 15) + 16 * grank) * 16 + t;
        } else {
            int exc = csize[cell] - CAP;
            int exb = exoff[cell] - exc;
            p = ufp[exb + (grank - CAP)];
        }
        int dstPos = layerBase + baseL + p;
        g_idx[dstPos]  = pk;
        g_coef[dstPos] = make_uint2(c01, c23);
        if (layer == 0)      d_inv1[baseL + tid] = (uint16_t)(baseL + p);
        else if (layer == 1) d_inv2[baseL + tid] = (uint16_t)(baseL + p);
    }
}

// ---- remap: rewrite layer-2/3 gather indices into dealt position space -----
__global__ void remap_kernel()
{
    int s = blockIdx.x * blockDim.x + threadIdx.x;
    if (s >= D2 + D3) return;
    int idx = D1 + s;                              // position in g_idx
    uint32_t pk = g_idx[idx];
    uint32_t a, b;
    if (s < D2) { a = d_inv1[pk & 0xffffu]; b = d_inv1[pk >> 16]; }
    else        { a = d_inv2[pk & 0xffffu]; b = d_inv2[pk >> 16]; }
    g_idx[idx] = a | (b << 16);
}

// -------- main kernel: R8 structure (coalesced stores), dealt gathers -------
// Metadata is produced by PRIOR launches, so __ldg is legal here.

struct NeuronIn {
    uint32_t pk, u01, u23;
    uint2 a, b;
};

__device__ __forceinline__ void fetch_neuron(const uint2* __restrict__ src,
                                             int mj, NeuronIn& n)
{
    n.pk = __ldg(&g_idx[mj]);
    uint2 cc = __ldg(&g_coef[mj]);
    n.u01 = cc.x;
    n.u23 = cc.y;
    n.a = src[n.pk & 0xffffu];
    n.b = src[n.pk >> 16];
}

__device__ __forceinline__ uint2 neuron_math(const NeuronIn& n)
{
    float2 c01 = __half22float2(*reinterpret_cast<const __half2*>(&n.u01));
    float2 c23 = __half22float2(*reinterpret_cast<const __half2*>(&n.u23));
    uint2 o;
#pragma unroll
    for (int r = 0; r < 2; r++) {
        uint32_t ua = (r == 0) ? n.a.x : n.a.y;
        uint32_t ub = (r == 0) ? n.b.x : n.b.y;
        float2 a = __half22float2(*reinterpret_cast<const __half2*>(&ua));
        float2 b = __half22float2(*reinterpret_cast<const __half2*>(&ub));
        float o0 = fmaf(fmaf(c23.y, b.x, c01.y), a.x, fmaf(c23.x, b.x, c01.x));
        float o1 = fmaf(fmaf(c23.y, b.y, c01.y), a.y, fmaf(c23.x, b.y, c01.x));
        __half2 h = __floats2half2_rn(o0, o1);
        uint32_t uh = *reinterpret_cast<uint32_t*>(&h);
        if (r == 0) o.x = uh; else o.y = uh;
    }
    return o;
}

__device__ __forceinline__ void run_layer(const uint2* __restrict__ src,
                                          uint2* __restrict__ dst,
                                          int metaBase, int D, int tid)
{
    const int iters = D / NTHREADS;
    NeuronIn cur, nxt;
    int j = tid;
    fetch_neuron(src, metaBase + j, cur);
#pragma unroll 2
    for (int it = 0; it < iters - 1; it++) {
        fetch_neuron(src, metaBase + j + NTHREADS, nxt);
        dst[j] = neuron_math(cur);
        cur = nxt;
        j += NTHREADS;
    }
    dst[j] = neuron_math(cur);
}

__global__ void __launch_bounds__(NTHREADS, 1)
diff_logic_main(const float* __restrict__ x, float* __restrict__ out)
{
    extern __shared__ __align__(16) uint32_t smem_raw[];
    uint2* xs = reinterpret_cast<uint2*>(smem_raw);
    uint2* h1 = xs + D0;
    uint2* h2 = h1 + D1;
    float* wacc = reinterpret_cast<float*>(h2 + D2);

    const int tid  = threadIdx.x;
    const int row0 = blockIdx.x * ROWS;

    {
        int col = tid;                            // D0 == NTHREADS
        float v0 = x[(size_t)(row0 + 0) * D0 + col];
        float v1 = x[(size_t)(row0 + 1) * D0 + col];
        float v2 = x[(size_t)(row0 + 2) * D0 + col];
        float v3 = x[(size_t)(row0 + 3) * D0 + col];
        __half2 p0 = __floats2half2_rn(v0, v1);
        __half2 p1 = __floats2half2_rn(v2, v3);
        uint2 slot;
        slot.x = *reinterpret_cast<uint32_t*>(&p0);
        slot.y = *reinterpret_cast<uint32_t*>(&p1);
        xs[col] = slot;
    }
    __syncthreads();

    run_layer(xs, h1, 0, D1, tid);
    __syncthreads();
    run_layer(h1, h2, D1, D2, tid);
    __syncthreads();

    // Layer 3 fused with group-sum (position perm stays within each group).
    const int lane = tid & 31;
    const int warp = tid >> 5;

    for (int g = 0; g < KCLS; g++) {
        float acc[ROWS];
#pragma unroll
        for (int r = 0; r < ROWS; r++) acc[r] = 0.f;
        {
            int mj = D1 + D2 + g * GRP + tid;     // GRP == NTHREADS
            NeuronIn n;
            fetch_neuron(h2, mj, n);
            float2 c01 = __half22float2(*reinterpret_cast<const __half2*>(&n.u01));
            float2 c23 = __half22float2(*reinterpret_cast<const __half2*>(&n.u23));
#pragma unroll
            for (int r = 0; r < 2; r++) {
                uint32_t ua = (r == 0) ? n.a.x : n.a.y;
                uint32_t ub = (r == 0) ? n.b.x : n.b.y;
                float2 a = __half22float2(*reinterpret_cast<const __half2*>(&ua));
                float2 b = __half22float2(*reinterpret_cast<const __half2*>(&ub));
                acc[2 * r + 0] = fmaf(fmaf(c23.y, b.x, c01.y), a.x, fmaf(c23.x, b.x, c01.x));
                acc[2 * r + 1] = fmaf(fmaf(c23.y, b.y, c01.y), a.y, fmaf(c23.x, b.y, c01.x));
            }
        }
#pragma unroll
        for (int r = 0; r < ROWS; r++) {
#pragma unroll
            for (int off = 16; off > 0; off >>= 1)
                acc[r] += __shfl_down_sync(0xffffffffu, acc[r], off);
        }
        if (lane == 0) {
#pragma unroll
            for (int r = 0; r < ROWS; r++)
                wacc[(g * NWARP + warp) * ROWS + r] = acc[r];
        }
    }
    __syncthreads();

    if (tid < KCLS * ROWS) {
        int g = tid / ROWS;
        int r = tid - g * ROWS;
        float s = 0.f;
#pragma unroll
        for (int w = 0; w < NWARP; w++)
            s += wacc[(g * NWARP + w) * ROWS + r];
        out[(size_t)(row0 + r) * KCLS + g] = s * (1.f / TAU);
    }
}

// -----------------------------------------------------------------------------

extern "C" void kernel_launch(void* const* d_in, const int* in_sizes, int n_in,
                              void* d_out, int out_size)
{
    (void)in_sizes; (void)n_in; (void)out_size;
    const float* x  = (const float*)d_in[0];
    const float* w1 = (const float*)d_in[1];
    const float* w2 = (const float*)d_in[2];
    const float* w3 = (const float*)d_in[3];
    const int* ia1 = (const int*)d_in[4];
    const int* ib1 = (const int*)d_in[5];
    const int* ia2 = (const int*)d_in[6];
    const int* ib2 = (const int*)d_in[7];
    const int* ia3 = (const int*)d_in[8];
    const int* ib3 = (const int*)d_in[9];
    float* out = (float*)d_out;

    precompute_kernel<<<(NNEUR + 255) / 256, 256>>>(w1, w2, w3, ia1, ib1, ia2, ib2, ia3, ib3);
    build_deal_kernel<<<NCHUNK, 1024>>>();                     // 26 independent CTAs
    remap_kernel<<<(D2 + D3 + 255) / 256, 256>>>();            // fix layer-2/3 indices

    size_t smem = (size_t)(D0 + D1 + D2) * sizeof(uint2)
                + (size_t)(KCLS * NWARP * ROWS) * sizeof(float);   // 144,384 B
    cudaFuncSetAttribute(diff_logic_main, cudaFuncAttributeMaxDynamicSharedMemorySize, (int)smem);

    diff_logic_main<<<B_SZ / ROWS, NTHREADS, smem>>>(x, out);
}

// round 13
// speedup vs baseline: 1.0341x; 1.0341x over previous
#include <cuda_runtime.h>
#include <cuda_fp16.h>
#include <stdint.h>

#define B_SZ     4096
#define D0       1024
#define D1       8192
#define D2       8192
#define D3       10240
#define NNEUR    (D1 + D2 + D3)     // 26624
#define KCLS     10
#define GRP      (D3 / KCLS)        // 1024
#define TAU      30.0f
#define ROWS     4
#define NTHREADS 1024
#define NWARP    (NTHREADS / 32)    // 32
#define CELLS    256                // 16 a-bank-pairs x 16 b-bank-pairs
#define CHUNK    1024
#define CAP      (CHUNK / CELLS)    // 4
#define NCHUNK   (NNEUR / CHUNK)    // 26
#define SCNSTR   40                 // 32 warps + pad

// -------- inverse perms + stage counters + final metadata --------
__device__ uint16_t d_inv1[D1];     // layer-1: orig -> dealt pos (layer-local)
__device__ uint16_t d_inv2[D2];
__device__ int      d_cnt[4];       // [0]=L1 meta+inv1, [1]=inv2, [2]=L2 meta, [3]=L3 meta
__device__ uint32_t g_idx[NNEUR];   // ia | (ib<<16), dealt-position space
__device__ uint2    g_coef[NNEUR];  // {half2(c0,c1), half2(c2,c3)}

__constant__ float OPC[16][4] = {
    {0.f, 0.f, 0.f, 0.f}, {0.f, 0.f, 0.f, 1.f}, {0.f, 1.f, 0.f, -1.f}, {0.f, 1.f, 0.f, 0.f},
    {0.f, 0.f, 1.f, -1.f}, {0.f, 0.f, 1.f, 0.f}, {0.f, 1.f, 1.f, -2.f}, {0.f, 1.f, 1.f, -1.f},
    {1.f, -1.f, -1.f, 1.f}, {1.f, -1.f, -1.f, 2.f}, {1.f, 0.f, -1.f, 0.f}, {1.f, 0.f, -1.f, 1.f},
    {1.f, -1.f, 0.f, 0.f}, {1.f, -1.f, 0.f, 1.f}, {1.f, 0.f, 0.f, -1.f}, {1.f, 0.f, 0.f, 0.f}};

// ---- acquire-poll with backoff on a stage counter, then CTA barrier --------
__device__ __forceinline__ void wait_cnt(int idx, int target)
{
    if (threadIdx.x == 0) {
        int v;
        asm volatile("ld.acquire.gpu.global.b32 %0, [%1];"
                     : "=r"(v) : "l"(&d_cnt[idx]) : "memory");
        while (v < target) {
            __nanosleep(256);
            asm volatile("ld.acquire.gpu.global.b32 %0, [%1];"
                         : "=r"(v) : "l"(&d_cnt[idx]) : "memory");
        }
    }
    __syncthreads();
}

__device__ __forceinline__ void publish_cnt(int idx)
{
    __threadfence();
    __syncthreads();
    if (threadIdx.x == 0) atomicAdd(&d_cnt[idx], 1);
}

// ---- in-kernel builder: CTAs 0..25, one per 1024-neuron chunk, ALL parallel -
// Cell classification uses residue predictions derived from raw index data:
//   layer1: exact (x unpermuted):          ra = ia1[j]&15
//   layer2: inv1[a]&15 == ia1[a]&15 (unspilled, ~80%):  ra = ia1[ia2[j]]&15
//   layer3: inv2[a]&15 == t used by L2 deal == ia1[ia2[a]]&15 (~80%)
// Prediction affects only deal QUALITY; the permutation + remap are exact.
// Deal core: R8-validated (__match_any + warp-shuffle scans). Deterministic.
__device__ void do_build(int chunk, uint16_t* scratch,
                         const float* __restrict__ w1, const float* __restrict__ w2,
                         const float* __restrict__ w3,
                         const int* __restrict__ ia1, const int* __restrict__ ib1,
                         const int* __restrict__ ia2, const int* __restrict__ ib2,
                         const int* __restrict__ ia3, const int* __restrict__ ib3)
{
    uint16_t* off    = scratch;                          // CELLS*SCNSTR
    uint16_t* chbase = off + CELLS * SCNSTR;             // CELLS*4
    uint16_t* csize  = chbase + CELLS * 4;               // CELLS
    uint16_t* exoff  = csize + CELLS;                    // CELLS
    uint16_t* ufoff  = exoff + CELLS;                    // CELLS
    uint16_t* ufp    = ufoff + CELLS;                    // CHUNK
    int* wte = reinterpret_cast<int*>(ufp + CHUNK);      // 8
    int* wtu = wte + 8;                                  // 8

    const int tid  = threadIdx.x;
    const int lane = tid & 31;
    const int w    = tid >> 5;
    const uint32_t ltm = (1u << lane) - 1u;

    const int layer = (chunk < 8) ? 0 : ((chunk < 16) ? 1 : 2);
    const int layerBase = (layer == 0) ? 0 : ((layer == 1) ? D1 : (D1 + D2));
    const int baseL = (chunk - ((layer == 0) ? 0 : ((layer == 1) ? 8 : 16))) * CHUNK;
    const int j = baseL + tid;                            // layer-local neuron id

    // ---- own metadata: indices + softmax coefficients ----
    int ia, ib; const float* wp;
    uint32_t ra, rb;
    if (layer == 0) {
        ia = __ldg(&ia1[j]); ib = __ldg(&ib1[j]); wp = w1 + (size_t)j * 16;
        ra = (uint32_t)ia & 15u; rb = (uint32_t)ib & 15u;
    } else if (layer == 1) {
        ia = __ldg(&ia2[j]); ib = __ldg(&ib2[j]); wp = w2 + (size_t)j * 16;
        ra = (uint32_t)__ldg(&ia1[ia]) & 15u; rb = (uint32_t)__ldg(&ia1[ib]) & 15u;
    } else {
        ia = __ldg(&ia3[j]); ib = __ldg(&ib3[j]); wp = w3 + (size_t)j * 16;
        ra = (uint32_t)__ldg(&ia1[__ldg(&ia2[ia])]) & 15u;
        rb = (uint32_t)__ldg(&ia1[__ldg(&ia2[ib])]) & 15u;
    }

    float v[16]; float m = -3.4e38f;
#pragma unroll
    for (int i = 0; i < 16; i++) { v[i] = wp[i]; m = fmaxf(m, v[i]); }
    float s = 0.f;
#pragma unroll
    for (int i = 0; i < 16; i++) { v[i] = expf(v[i] - m); s += v[i]; }
    float inv = 1.f / s;
    float c0 = 0.f, c1 = 0.f, c2 = 0.f, c3 = 0.f;
#pragma unroll
    for (int i = 0; i < 16; i++) {
        float p = v[i] * inv;
        c0 = fmaf(p, OPC[i][0], c0);
        c1 = fmaf(p, OPC[i][1], c1);
        c2 = fmaf(p, OPC[i][2], c2);
        c3 = fmaf(p, OPC[i][3], c3);
    }
    __half2 h01 = __floats2half2_rn(c0, c1);
    __half2 h23 = __floats2half2_rn(c2, c3);
    uint2 coef = make_uint2(*reinterpret_cast<uint32_t*>(&h01),
                            *reinterpret_cast<uint32_t*>(&h23));

    // ---- deal ----
    for (int i = tid; i < CELLS * SCNSTR / 2; i += NTHREADS)
        reinterpret_cast<uint32_t*>(off)[i] = 0;
    __syncthreads();

    int cell = (int)(ra * 16u + rb);
    uint32_t mask = __match_any_sync(0xffffffffu, cell);
    int lr = __popc(mask & ltm);
    if ((mask & ltm) == 0)
        off[cell * SCNSTR + w] = (uint16_t)__popc(mask);
    __syncthreads();

    {   // phase 1: per-(cell, 8-warp chunk) exclusive scan
        int c  = tid >> 2;
        int ch = tid & 3;
        int bo = c * SCNSTR + ch * 8;
        uint16_t run = 0;
#pragma unroll
        for (int i = 0; i < 8; i++) {
            uint16_t t = off[bo + i];
            off[bo + i] = run;
            run = (uint16_t)(run + t);
        }
        chbase[c * 4 + ch] = run;
    }
    __syncthreads();

    if (tid < CELLS) {   // phase 2: per-cell combine
        int c = tid; uint16_t bb = 0;
#pragma unroll
        for (int ch = 0; ch < 4; ch++) {
            uint16_t t = chbase[c * 4 + ch];
            chbase[c * 4 + ch] = bb;
            bb = (uint16_t)(bb + t);
        }
        csize[c] = bb;
        exoff[c] = (bb > CAP) ? (uint16_t)(bb - CAP) : 0;
        ufoff[c] = (bb < CAP) ? (uint16_t)(CAP - bb) : 0;
    }
    __syncthreads();

    {   // inclusive scans over 256 cells via warp shuffles
        int e = 0, u = 0;
        if (tid < CELLS) {
            e = exoff[tid]; u = ufoff[tid];
#pragma unroll
            for (int o = 1; o < 32; o <<= 1) {
                int pe = __shfl_up_sync(0xffffffffu, e, o);
                int pu = __shfl_up_sync(0xffffffffu, u, o);
                if (lane >= o) { e += pe; u += pu; }
            }
            if (lane == 31) { wte[w] = e; wtu[w] = u; }
        }
        __syncthreads();
        if (tid == 0) {
            int be = 0, bu = 0;
#pragma unroll
            for (int i = 0; i < 8; i++) {
                int te = wte[i], tu = wtu[i];
                wte[i] = be; wtu[i] = bu;
                be += te; bu += tu;
            }
        }
        __syncthreads();
        if (tid < CELLS) {
            exoff[tid] = (uint16_t)(e + wte[w]);
            ufoff[tid] = (uint16_t)(u + wtu[w]);
        }
    }
    __syncthreads();

    if (tid < CELLS) {   // emit unfilled dealt positions, grouped by cell
        int c = tid, t = c >> 4, ss = c & 15;
        int sz  = csize[c];
        int ufc = (sz < CAP) ? CAP - sz : 0;
        int ub  = ufoff[c] - ufc;
        for (int mm = sz; mm < CAP; mm++)
            ufp[ub + (mm - sz)] = (uint16_t)((((ss - t) & 15) + 16 * mm) * 16 + t);
    }
    __syncthreads();

    int p;
    {   // assign position
        int grank = off[cell * SCNSTR + w] + chbase[cell * 4 + (w >> 3)] + lr;
        int t = cell >> 4, ss = cell & 15;
        if (grank < CAP) {
            p = (((ss - t) & 15) + 16 * grank) * 16 + t;
        } else {
            int exc = csize[cell] - CAP;
            int exb = exoff[cell] - exc;
            p = ufp[exb + (grank - CAP)];
        }
    }
    const int dstPos = layerBase + baseL + p;

    // ---- publish (inv first: it has NO cross-layer dependency) ----
    if (layer == 0) {
        d_inv1[j] = (uint16_t)(baseL + p);
        g_idx[dstPos]  = (uint32_t)ia | ((uint32_t)ib << 16);   // x unpermuted
        g_coef[dstPos] = coef;
        publish_cnt(0);                         // L1 meta + inv1 ready
    } else if (layer == 1) {
        d_inv2[j] = (uint16_t)(baseL + p);
        publish_cnt(1);                         // inv2 ready (no wait needed!)
        wait_cnt(0, 8);                         // need inv1 to finalize indices
        uint32_t a = d_inv1[ia], b = d_inv1[ib];
        g_idx[dstPos]  = a | (b << 16);
        g_coef[dstPos] = coef;
        publish_cnt(2);                         // L2 meta ready
    } else {
        wait_cnt(1, 8);                         // need inv2
        uint32_t a = d_inv2[ia], b = d_inv2[ib];
        g_idx[dstPos]  = a | (b << 16);
        g_coef[dstPos] = coef;
        publish_cnt(3);                         // L3 meta ready
    }
}

// -------- main compute (R8 structure; coherent metadata loads — R10 lesson) -

struct NeuronIn {
    uint32_t pk, u01, u23;
    uint2 a, b;
};

__device__ __forceinline__ void fetch_neuron(const uint2* __restrict__ src,
                                             int mj, NeuronIn& n)
{
    n.pk = g_idx[mj];                 // produced in THIS kernel: no __ldg
    uint2 cc = g_coef[mj];
    n.u01 = cc.x;
    n.u23 = cc.y;
    n.a = src[n.pk & 0xffffu];
    n.b = src[n.pk >> 16];
}

__device__ __forceinline__ uint2 neuron_math(const NeuronIn& n)
{
    float2 c01 = __half22float2(*reinterpret_cast<const __half2*>(&n.u01));
    float2 c23 = __half22float2(*reinterpret_cast<const __half2*>(&n.u23));
    uint2 o;
#pragma unroll
    for (int r = 0; r < 2; r++) {
        uint32_t ua = (r == 0) ? n.a.x : n.a.y;
        uint32_t ub = (r == 0) ? n.b.x : n.b.y;
        float2 a = __half22float2(*reinterpret_cast<const __half2*>(&ua));
        float2 b = __half22float2(*reinterpret_cast<const __half2*>(&ub));
        float o0 = fmaf(fmaf(c23.y, b.x, c01.y), a.x, fmaf(c23.x, b.x, c01.x));
        float o1 = fmaf(fmaf(c23.y, b.y, c01.y), a.y, fmaf(c23.x, b.y, c01.x));
        __half2 h = __floats2half2_rn(o0, o1);
        uint32_t uh = *reinterpret_cast<uint32_t*>(&h);
        if (r == 0) o.x = uh; else o.y = uh;
    }
    return o;
}

__device__ __forceinline__ void run_layer(const uint2* __restrict__ src,
                                          uint2* __restrict__ dst,
                                          int metaBase, int D, int tid)
{
    const int iters = D / NTHREADS;
    NeuronIn cur, nxt;
    int j = tid;
    fetch_neuron(src, metaBase + j, cur);
#pragma unroll 2
    for (int it = 0; it < iters - 1; it++) {
        fetch_neuron(src, metaBase + j + NTHREADS, nxt);
        dst[j] = neuron_math(cur);
        cur = nxt;
        j += NTHREADS;
    }
    dst[j] = neuron_math(cur);
}

__global__ void __launch_bounds__(NTHREADS, 1)
diff_logic_main(const float* __restrict__ x, float* __restrict__ out,
                const float* __restrict__ w1, const float* __restrict__ w2,
                const float* __restrict__ w3,
                const int* __restrict__ ia1, const int* __restrict__ ib1,
                const int* __restrict__ ia2, const int* __restrict__ ib2,
                const int* __restrict__ ia3, const int* __restrict__ ib3)
{
    extern __shared__ __align__(16) uint32_t smem_raw[];
    uint2* xs = reinterpret_cast<uint2*>(smem_raw);
    uint2* h1 = xs + D0;
    uint2* h2 = h1 + D1;
    float* wacc = reinterpret_cast<float*>(h2 + D2);

    const int tid  = threadIdx.x;
    const int bid  = blockIdx.x;
    const int row0 = bid * ROWS;

    {
        int col = tid;                            // D0 == NTHREADS
        float v0 = __ldg(&x[(size_t)(row0 + 0) * D0 + col]);
        float v1 = __ldg(&x[(size_t)(row0 + 1) * D0 + col]);
        float v2 = __ldg(&x[(size_t)(row0 + 2) * D0 + col]);
        float v3 = __ldg(&x[(size_t)(row0 + 3) * D0 + col]);
        __half2 p0 = __floats2half2_rn(v0, v1);
        __half2 p1 = __floats2half2_rn(v2, v3);
        uint2 slot;
        slot.x = *reinterpret_cast<uint32_t*>(&p0);
        slot.y = *reinterpret_cast<uint32_t*>(&p1);
        xs[col] = slot;
    }
    __syncthreads();

    // Builder CTAs (all wave-1 resident; 26 < 148 SMs, 1 CTA/SM) construct the
    // dealt metadata in parallel. Scratch aliases h1 (unused until compute, and
    // scratch use ends before any wait on this CTA's own compute path).
    if (bid < NCHUNK)
        do_build(bid, reinterpret_cast<uint16_t*>(h1),
                 w1, w2, w3, ia1, ib1, ia2, ib2, ia3, ib3);

    wait_cnt(0, 8);
    run_layer(xs, h1, 0, D1, tid);
    __syncthreads();

    wait_cnt(2, 8);
    run_layer(h1, h2, D1, D2, tid);
    __syncthreads();

    wait_cnt(3, 10);
    // Layer 3 fused with group-sum (position perm stays within each group).
    const int lane = tid & 31;
    const int warp = tid >> 5;

    for (int g = 0; g < KCLS; g++) {
        float acc[ROWS];
#pragma unroll
        for (int r = 0; r < ROWS; r++) acc[r] = 0.f;
        {
            int mj = D1 + D2 + g * GRP + tid;     // GRP == NTHREADS
            NeuronIn n;
            fetch_neuron(h2, mj, n);
            float2 c01 = __half22float2(*reinterpret_cast<const __half2*>(&n.u01));
            float2 c23 = __half22float2(*reinterpret_cast<const __half2*>(&n.u23));
#pragma unroll
            for (int r = 0; r < 2; r++) {
                uint32_t ua = (r == 0) ? n.a.x : n.a.y;
                uint32_t ub = (r == 0) ? n.b.x : n.b.y;
                float2 a = __half22float2(*reinterpret_cast<const __half2*>(&ua));
                float2 b = __half22float2(*reinterpret_cast<const __half2*>(&ub));
                acc[2 * r + 0] = fmaf(fmaf(c23.y, b.x, c01.y), a.x, fmaf(c23.x, b.x, c01.x));
                acc[2 * r + 1] = fmaf(fmaf(c23.y, b.y, c01.y), a.y, fmaf(c23.x, b.y, c01.x));
            }
        }
#pragma unroll
        for (int r = 0; r < ROWS; r++) {
#pragma unroll
            for (int off = 16; off > 0; off >>= 1)
                acc[r] += __shfl_down_sync(0xffffffffu, acc[r], off);
        }
        if (lane == 0) {
#pragma unroll
            for (int r = 0; r < ROWS; r++)
                wacc[(g * NWARP + warp) * ROWS + r] = acc[r];
        }
    }
    __syncthreads();

    if (tid < KCLS * ROWS) {
        int g = tid / ROWS;
        int r = tid - g * ROWS;
        float s = 0.f;
#pragma unroll
        for (int w = 0; w < NWARP; w++)
            s += wacc[(g * NWARP + w) * ROWS + r];
        out[(size_t)(row0 + r) * KCLS + g] = s * (1.f / TAU);
    }
}

// -----------------------------------------------------------------------------

extern "C" void kernel_launch(void* const* d_in, const int* in_sizes, int n_in,
                              void* d_out, int out_size)
{
    (void)in_sizes; (void)n_in; (void)out_size;
    const float* x  = (const float*)d_in[0];
    const float* w1 = (const float*)d_in[1];
    const float* w2 = (const float*)d_in[2];
    const float* w3 = (const float*)d_in[3];
    const int* ia1 = (const int*)d_in[4];
    const int* ib1 = (const int*)d_in[5];
    const int* ia2 = (const int*)d_in[6];
    const int* ib2 = (const int*)d_in[7];
    const int* ia3 = (const int*)d_in[8];
    const int* ib3 = (const int*)d_in[9];
    float* out = (float*)d_out;

    // reset stage counters: graph memset node (no kernel, no alloc)
    void* cntPtr = nullptr;
    cudaGetSymbolAddress(&cntPtr, d_cnt);
    cudaMemsetAsync(cntPtr, 0, 4 * sizeof(int));

    size_t smem = (size_t)(D0 + D1 + D2) * sizeof(uint2)
                + (size_t)(KCLS * NWARP * ROWS) * sizeof(float);   // 144,384 B
    cudaFuncSetAttribute(diff_logic_main, cudaFuncAttributeMaxDynamicSharedMemorySize, (int)smem);

    diff_logic_main<<<B_SZ / ROWS, NTHREADS, smem>>>(
        x, out, w1, w2, w3, ia1, ib1, ia2, ib2, ia3, ib3);
}